// round 14
// baseline (speedup 1.0000x reference)
#include <cuda_runtime.h>

typedef unsigned long long u64;
typedef unsigned int u32;

#define B_SZ 256
#define N_SZ 50
#define NN   (N_SZ * N_SZ)
#define MAX_ATTR 2000
#define NEGV (-9e15f)
#define NTHREADS 512
#define ATTR_ROWS 8
#define HBSTR 528               // bytes per hb16 row (264 bf16)
#define HUSTR 65                // u64 stride per fp32 h row
#define ASTR  56                // alpha row stride (f32)

// ---- dynamic smem layout (session) -----------------------------------------
#define OFF_HB16  0
#define SZ_HB16   (56 * HBSTR)                 // 29568
#define OFF_HU    (OFF_HB16 + SZ_HB16)
#define SZ_HU     (N_SZ * HUSTR * 8)           // 26000
#define OFF_AB2   (OFF_HU + SZ_HU)
#define SZ_AB2    (4 * 16 * 4 * 8)             // 2048
#define OFF_ALPHA (OFF_AB2 + SZ_AB2)
#define SZ_ALPHA  (N_SZ * ASTR * 4)            // 11200
#define OFF_ADJ   (OFF_ALPHA + SZ_ALPHA)
#define SZ_ADJ    2560
#define SMEM_DYN  (OFF_ADJ + SZ_ADJ)           // 71376

// ---- helpers ---------------------------------------------------------------
__device__ __forceinline__ u64 f2_fma(u64 a, u64 b, u64 c) {
    u64 d; asm("fma.rn.f32x2 %0,%1,%2,%3;" : "=l"(d) : "l"(a), "l"(b), "l"(c)); return d;
}
__device__ __forceinline__ u64 f2_abs(u64 a) { return a & 0x7FFFFFFF7FFFFFFFull; }
__device__ __forceinline__ u64 f2_dup(float a) {
    u64 d; asm("mov.b64 %0,{%1,%1};" : "=l"(d) : "f"(a)); return d;
}
__device__ __forceinline__ float2 f2_unpack(u64 a) {
    float2 r; asm("mov.b64 {%0,%1},%2;" : "=f"(r.x), "=f"(r.y) : "l"(a)); return r;
}
__device__ __forceinline__ u32 bpack(float lo, float hi) {
    u32 r; asm("cvt.rn.bf16x2.f32 %0,%1,%2;" : "=r"(r) : "f"(hi), "f"(lo)); return r;
}
__device__ __forceinline__ u32 bcvt(u64 v) {
    float2 p = f2_unpack(v); return bpack(p.x, p.y);
}
__device__ __forceinline__ u32 bmul(u32 a, u32 b) {
    u32 d; asm("mul.bf16x2 %0,%1,%2;" : "=r"(d) : "r"(a), "r"(b)); return d;
}
__device__ __forceinline__ u32 s2u(const void* p) {
    u32 a; asm("{.reg .u64 t; cvta.to.shared.u64 t,%1; cvt.u32.u64 %0,t;}" : "=r"(a) : "l"(p));
    return a;
}
__device__ __forceinline__ void ldsm4(u32& r0, u32& r1, u32& r2, u32& r3, u32 addr) {
    asm volatile("ldmatrix.sync.aligned.m8n8.x4.shared.b16 {%0,%1,%2,%3},[%4];"
                 : "=r"(r0), "=r"(r1), "=r"(r2), "=r"(r3) : "r"(addr));
}
__device__ __forceinline__ void ldsm2(u32& r0, u32& r1, u32 addr) {
    asm volatile("ldmatrix.sync.aligned.m8n8.x2.shared.b16 {%0,%1},[%2];"
                 : "=r"(r0), "=r"(r1) : "r"(addr));
}
__device__ __forceinline__ void mma16816(float& d0, float& d1, float& d2, float& d3,
                                         u32 a0, u32 a1, u32 a2, u32 a3, u32 b0, u32 b1) {
    asm("mma.sync.aligned.m16n8k16.row.col.f32.bf16.bf16.f32 "
        "{%0,%1,%2,%3},{%4,%5,%6,%7},{%8,%9},{%0,%1,%2,%3};"
        : "+f"(d0), "+f"(d1), "+f"(d2), "+f"(d3)
        : "r"(a0), "r"(a1), "r"(a2), "r"(a3), "r"(b0), "r"(b1));
}

extern __shared__ char dynsm[];

// phase-4 multi-row worker
template<int NR>
__device__ __forceinline__ void quad_rows(const u64* __restrict__ hu,
                                          const float* __restrict__ alpha,
                                          u64* __restrict__ outu,
                                          int bb, int r0, int lane)
{
    u64 acc[NR][2];
    #pragma unroll
    for (int r = 0; r < NR; ++r) { acc[r][0] = 0; acc[r][1] = 0; }
    #pragma unroll 2
    for (int jb = 0; jb < 12; ++jb) {
        float4 a4[NR];
        #pragma unroll
        for (int r = 0; r < NR; ++r)
            a4[r] = *(const float4*)(alpha + (r0 + r) * ASTR + jb * 4);
        #pragma unroll
        for (int jj = 0; jj < 4; ++jj) {
            int j = jb * 4 + jj;
            u64 hlo = hu[j * HUSTR + lane];
            u64 hhi = hu[j * HUSTR + 32 + lane];
            #pragma unroll
            for (int r = 0; r < NR; ++r) {
                float av = (jj == 0) ? a4[r].x : (jj == 1) ? a4[r].y : (jj == 2) ? a4[r].z : a4[r].w;
                u64 c = f2_dup(av);
                acc[r][0] = f2_fma(c, hlo, acc[r][0]);
                acc[r][1] = f2_fma(c, hhi, acc[r][1]);
            }
        }
    }
    #pragma unroll
    for (int jj = 0; jj < 2; ++jj) {              // tail j = 48, 49
        int j = 48 + jj;
        u64 hlo = hu[j * HUSTR + lane];
        u64 hhi = hu[j * HUSTR + 32 + lane];
        #pragma unroll
        for (int r = 0; r < NR; ++r) {
            u64 c = f2_dup(alpha[(r0 + r) * ASTR + j]);
            acc[r][0] = f2_fma(c, hlo, acc[r][0]);
            acc[r][1] = f2_fma(c, hhi, acc[r][1]);
        }
    }
    size_t ob = (size_t)bb * (N_SZ * 64);
    #pragma unroll
    for (int r = 0; r < NR; ++r) {
        outu[ob + (r0 + r) * 64 + lane]      = acc[r][0];
        outu[ob + (r0 + r) * 64 + 32 + lane] = acc[r][1];
    }
}

// select accumulator by adj code c in 1..4
__device__ __forceinline__ float ksel(float d0, float d1, float d2, float d3, int c) {
    float v = d0;
    v = (c == 2) ? d1 : v;
    v = (c == 3) ? d2 : v;
    v = (c == 4) ? d3 : v;
    return v;
}

__global__ __launch_bounds__(NTHREADS, 2)
void session_graph_kernel(const int* __restrict__ inputs,
                          const int* __restrict__ adj,
                          const float* __restrict__ A_attr,
                          const float* __restrict__ emb,
                          const float* __restrict__ attr_emb,
                          const float* __restrict__ a0,
                          const float* __restrict__ a1,
                          const float* __restrict__ a2,
                          const float* __restrict__ a3,
                          float* __restrict__ out)
{
    const int tid  = threadIdx.x;
    const int bb   = blockIdx.x;
    const int warp = tid >> 5;
    const int lane = tid & 31;
    const int gq   = lane >> 2;
    const int tq   = lane & 3;
    u64* outu = (u64*)out;

    float* alpha = (float*)(dynsm + OFF_ALPHA);
    unsigned char* adjb = (unsigned char*)(dynsm + OFF_ADJ);
    const u64* hu = (const u64*)(dynsm + OFF_HU);

    // ---------------- staging -----------------------------------------
    if (tid < 256) {
        int k = tid >> 6, r = tid & 63, ks = r >> 2, q = r & 3;
        const float* a = (k == 0) ? a0 : (k == 1) ? a1 : (k == 2) ? a2 : a3;
        float s = (ks < 8) ? 0.6f : 0.4f;
        int bc = (ks & 7) * 16;
        u32 lo = bpack(s * a[bc + 2 * q],     s * a[bc + 2 * q + 1]);
        u32 hi = bpack(s * a[bc + 8 + 2 * q], s * a[bc + 8 + 2 * q + 1]);
        *(u64*)(dynsm + OFF_AB2 + ((k * 16 + ks) * 4 + q) * 8) = ((u64)hi << 32) | lo;
    }
    {
        const int4* ag4 = (const int4*)(adj + bb * NN);
        u32* adjw = (u32*)adjb;
        for (int idx = tid; idx < NN / 4; idx += NTHREADS) {
            int4 v = ag4[idx];
            adjw[idx] = (u32)(v.x & 255) | ((u32)(v.y & 255) << 8) |
                        ((u32)(v.z & 255) << 16) | ((u32)(v.w & 255) << 24);
        }
    }
    {
        const int* inrow = inputs + bb * N_SZ;
        const u64* embu = (const u64*)emb;
        for (int idx = tid; idx < N_SZ * 64; idx += NTHREADS) {
            int i = idx >> 6, c = idx & 63;
            int node = inrow[i];
            u64 e = embu[(size_t)node * 64 + c];
            *(u64*)(dynsm + OFF_HU + ((size_t)i * HUSTR + c) * 8) = e;
            *(u32*)(dynsm + OFF_HB16 + i * HBSTR + c * 4)       = bcvt(e);
            *(u32*)(dynsm + OFF_HB16 + i * HBSTR + 256 + c * 4) = bcvt(f2_abs(e));
        }
        for (int idx = tid; idx < 6 * 132; idx += NTHREADS) {    // zero rows 50..55
            int i = 50 + idx / 132, c = idx % 132;
            *(u32*)(dynsm + OFF_HB16 + i * HBSTR + c * 4) = 0;
        }
    }
    {
        float4 nv = make_float4(NEGV, NEGV, NEGV, NEGV);
        float4* al4 = (float4*)alpha;
        for (int idx = tid; idx < N_SZ * ASTR / 4; idx += NTHREADS)
            al4[idx] = nv;
    }
    __syncthreads();

    // ---------------- phase 2: ks outer, all 4 k inner (LDSM x1) -------
    {
        const u32 hbb = s2u(dynsm + OFF_HB16);
        const int grp = lane >> 3, rsel = lane & 7;
        const int ib = warp >> 2, np = warp & 3;
        int arow = ib * 16 + rsel + ((grp & 1) << 3);
        if (arow >= N_SZ) arow = 0;                     // discarded rows
        const u32 aaddr = hbb + arow * HBSTR + ((grp >> 1) << 4);
        const int nt0 = np * 2;
        const u32 baddr0 = hbb + (nt0 * 8 + rsel) * HBSTR + ((lane & 8) << 1);
        const u32 baddr1 = baddr0 + 8 * HBSTR;
        const bool pair = (np < 3);
        const int i0 = ib * 16 + gq, i1 = i0 + 8;
        const int j0 = nt0 * 8 + 2 * tq;
        const u64* abp = (const u64*)(dynsm + OFF_AB2) + tq;

        float dA[4][4], dB[4][4];
        #pragma unroll
        for (int k = 0; k < 4; ++k)
            #pragma unroll
            for (int x = 0; x < 4; ++x) { dA[k][x] = 0.f; dB[k][x] = 0.f; }

        #pragma unroll 4
        for (int ks = 0; ks < 16; ++ks) {
            u32 h0, h1, h2, h3;
            ldsm4(h0, h1, h2, h3, aaddr + ks * 32);
            u32 b0, b1, c0, c1;
            ldsm2(b0, b1, baddr0 + ks * 32);
            if (pair) ldsm2(c0, c1, baddr1 + ks * 32);
            #pragma unroll
            for (int k = 0; k < 4; ++k) {
                u64 ab = abp[k * 64 + ks * 4];
                u32 lo = (u32)ab, hi = (u32)(ab >> 32);
                u32 f0 = bmul(h0, lo), f1 = bmul(h1, lo);
                u32 f2 = bmul(h2, hi), f3 = bmul(h3, hi);
                mma16816(dA[k][0], dA[k][1], dA[k][2], dA[k][3], f0, f1, f2, f3, b0, b1);
                if (pair)
                    mma16816(dB[k][0], dB[k][1], dB[k][2], dB[k][3], f0, f1, f2, f3, c0, c1);
            }
        }

        // epilogue: one adj read + k-select per cell
        #pragma unroll
        for (int pos = 0; pos < 4; ++pos) {
            int i = (pos < 2) ? i0 : i1;
            int j = j0 + (pos & 1);
            if (i < N_SZ && j < N_SZ) {
                int c = adjb[i * N_SZ + j];
                if (c) alpha[i * ASTR + j] =
                    ksel(dA[0][pos], dA[1][pos], dA[2][pos], dA[3][pos], c);
            }
            if (pair) {
                int j2 = j + 8;
                if (i < N_SZ && j2 < N_SZ) {
                    int c = adjb[i * N_SZ + j2];
                    if (c) alpha[i * ASTR + j2] =
                        ksel(dB[0][pos], dB[1][pos], dB[2][pos], dB[3][pos], c);
                }
            }
        }
    }
    __syncthreads();

    // ---------------- phase 3: row softmax ------------------------------
    for (int i = warp; i < N_SZ; i += 16) {
        float v0 = alpha[i * ASTR + lane];
        float v1 = (lane < N_SZ - 32) ? alpha[i * ASTR + 32 + lane] : NEGV;
        float m = fmaxf(v0, v1);
        #pragma unroll
        for (int off = 16; off > 0; off >>= 1)
            m = fmaxf(m, __shfl_xor_sync(0xFFFFFFFFu, m, off));
        float e0 = __expf(v0 - m);
        float e1 = (lane < N_SZ - 32) ? __expf(v1 - m) : 0.f;
        float ss = e0 + e1;
        #pragma unroll
        for (int off = 16; off > 0; off >>= 1)
            ss += __shfl_xor_sync(0xFFFFFFFFu, ss, off);
        float inv = 1.0f / ss;
        alpha[i * ASTR + lane] = e0 * inv;
        if (lane < N_SZ - 32)
            alpha[i * ASTR + 32 + lane] = e1 * inv;
    }
    __syncthreads();

    // ---------------- phase 4: out = alpha @ h (5 rows x 10 warps) -----
    // warps 10-15 skip straight to the attr tail (no smem/sync dependency)
    if (warp < 10) quad_rows<5>(hu, alpha, outu, bb, warp * 5, lane);

    // ---------------- attr tail: group bb>>3, K-slice bb&7 --------------
    // 8 rows x 250 k, weighted warp split (warps 10-15 take more k).
    {
        const int g     = bb >> 3;
        const int kbase = (bb & 7) * 250;
        const float* Arow = A_attr + (size_t)(g * ATTR_ROWS) * MAX_ATTR + kbase;
        const uint4* Wg = (const uint4*)attr_emb;

        int c0, c1;
        if (warp >= 10)    { c0 = 13 * (warp - 10);    c1 = c0 + 13; }   // 0..77
        else if (warp < 7) { c0 = 78 + 5 * warp;       c1 = c0 + 5;  }   // 78..112
        else               { c0 = 113 + 4 * (warp - 7); c1 = c0 + 4; }   // 113..124

        u64 acc[ATTR_ROWS][2];
        #pragma unroll
        for (int r = 0; r < ATTR_ROWS; ++r) { acc[r][0] = 0; acc[r][1] = 0; }

        for (int c = c0; c < c1; ++c) {
            int k = kbase + 2 * c;
            uint4 w0 = Wg[(size_t)k * 32 + lane];
            uint4 w1 = Wg[(size_t)(k + 1) * 32 + lane];
            u64 w0l = ((u64)w0.y << 32) | w0.x, w0h = ((u64)w0.w << 32) | w0.z;
            u64 w1l = ((u64)w1.y << 32) | w1.x, w1h = ((u64)w1.w << 32) | w1.z;
            #pragma unroll
            for (int r = 0; r < ATTR_ROWS; ++r) {
                float2 a = *(const float2*)(Arow + r * MAX_ATTR + 2 * c);
                u64 cx = f2_dup(a.x), cy = f2_dup(a.y);
                acc[r][0] = f2_fma(cx, w0l, acc[r][0]);
                acc[r][1] = f2_fma(cx, w0h, acc[r][1]);
                acc[r][0] = f2_fma(cy, w1l, acc[r][0]);
                acc[r][1] = f2_fma(cy, w1h, acc[r][1]);
            }
        }

        // accumulate into out (region pre-zeroed by memset); cols 4*lane..+3
        float* abase = out + (size_t)B_SZ * (N_SZ * 128)
                           + (size_t)g * ATTR_ROWS * 128 + 4 * lane;
        #pragma unroll
        for (int r = 0; r < ATTR_ROWS; ++r) {
            float2 v0 = f2_unpack(acc[r][0]);
            float2 v1 = f2_unpack(acc[r][1]);
            float* d = abase + r * 128;
            atomicAdd(d,     v0.x);
            atomicAdd(d + 1, v0.y);
            atomicAdd(d + 2, v1.x);
            atomicAdd(d + 3, v1.y);
        }
    }
}

extern "C" void kernel_launch(void* const* d_in, const int* in_sizes, int n_in,
                              void* d_out, int out_size)
{
    (void)in_sizes; (void)n_in; (void)out_size;
    const int*   inputs    = (const int*)  d_in[0];
    const int*   adj       = (const int*)  d_in[1];
    // d_in[2] = mask_item (unused by the reference computation)
    const float* A_attr    = (const float*)d_in[3];
    const float* emb       = (const float*)d_in[4];
    const float* attr_emb  = (const float*)d_in[5];
    const float* a0        = (const float*)d_in[6];
    const float* a1        = (const float*)d_in[7];
    const float* a2        = (const float*)d_in[8];
    const float* a3        = (const float*)d_in[9];
    float* out = (float*)d_out;

    // zero the attr_sess region (accumulated via atomics)
    cudaMemsetAsync(out + (size_t)B_SZ * N_SZ * 128, 0,
                    (size_t)B_SZ * 128 * sizeof(float));

    cudaFuncSetAttribute(session_graph_kernel,
                         cudaFuncAttributeMaxDynamicSharedMemorySize, SMEM_DYN);
    session_graph_kernel<<<B_SZ, NTHREADS, SMEM_DYN>>>(
        inputs, adj, A_attr, emb, attr_emb, a0, a1, a2, a3, out);
}

// round 15
// speedup vs baseline: 1.6199x; 1.6199x over previous
#include <cuda_runtime.h>

typedef unsigned long long u64;
typedef unsigned int u32;

#define B_SZ 256
#define N_SZ 50
#define NN   (N_SZ * N_SZ)
#define MAX_ATTR 2000
#define NEGV (-9e15f)
#define NTHREADS 512
#define ATTR_ROWS 8
#define HBSTR 528               // bytes per hb16 row (264 bf16)
#define HUSTR 65                // u64 stride per fp32 h row
#define ASTR  56                // alpha row stride (f32)

// ---- dynamic smem layout (session) -----------------------------------------
#define OFF_HB16  0
#define SZ_HB16   (56 * HBSTR)                 // 29568
#define OFF_HU    (OFF_HB16 + SZ_HB16)
#define SZ_HU     (N_SZ * HUSTR * 8)           // 26000
#define OFF_AB2   (OFF_HU + SZ_HU)
#define SZ_AB2    (4 * 16 * 4 * 8)             // 2048
#define OFF_ALPHA (OFF_AB2 + SZ_AB2)
#define SZ_ALPHA  (N_SZ * ASTR * 4)            // 11200
#define OFF_ADJ   (OFF_ALPHA + SZ_ALPHA)
#define SZ_ADJ    2560
#define SMEM_DYN  (OFF_ADJ + SZ_ADJ)           // 71376 (attr reduce aliases 0..65536)

// ---- helpers ---------------------------------------------------------------
__device__ __forceinline__ u64 f2_fma(u64 a, u64 b, u64 c) {
    u64 d; asm("fma.rn.f32x2 %0,%1,%2,%3;" : "=l"(d) : "l"(a), "l"(b), "l"(c)); return d;
}
__device__ __forceinline__ u64 f2_add(u64 a, u64 b) {
    u64 d; asm("add.rn.f32x2 %0,%1,%2;" : "=l"(d) : "l"(a), "l"(b)); return d;
}
__device__ __forceinline__ u64 f2_abs(u64 a) { return a & 0x7FFFFFFF7FFFFFFFull; }
__device__ __forceinline__ u64 f2_dup(float a) {
    u64 d; asm("mov.b64 %0,{%1,%1};" : "=l"(d) : "f"(a)); return d;
}
__device__ __forceinline__ float2 f2_unpack(u64 a) {
    float2 r; asm("mov.b64 {%0,%1},%2;" : "=f"(r.x), "=f"(r.y) : "l"(a)); return r;
}
__device__ __forceinline__ u32 bpack(float lo, float hi) {
    u32 r; asm("cvt.rn.bf16x2.f32 %0,%1,%2;" : "=r"(r) : "f"(hi), "f"(lo)); return r;
}
__device__ __forceinline__ u32 bcvt(u64 v) {
    float2 p = f2_unpack(v); return bpack(p.x, p.y);
}
__device__ __forceinline__ u32 bmul(u32 a, u32 b) {
    u32 d; asm("mul.bf16x2 %0,%1,%2;" : "=r"(d) : "r"(a), "r"(b)); return d;
}
__device__ __forceinline__ u32 s2u(const void* p) {
    u32 a; asm("{.reg .u64 t; cvta.to.shared.u64 t,%1; cvt.u32.u64 %0,t;}" : "=r"(a) : "l"(p));
    return a;
}
__device__ __forceinline__ void ldsm4(u32& r0, u32& r1, u32& r2, u32& r3, u32 addr) {
    asm volatile("ldmatrix.sync.aligned.m8n8.x4.shared.b16 {%0,%1,%2,%3},[%4];"
                 : "=r"(r0), "=r"(r1), "=r"(r2), "=r"(r3) : "r"(addr));
}
__device__ __forceinline__ void ldsm2(u32& r0, u32& r1, u32 addr) {
    asm volatile("ldmatrix.sync.aligned.m8n8.x2.shared.b16 {%0,%1},[%2];"
                 : "=r"(r0), "=r"(r1) : "r"(addr));
}
__device__ __forceinline__ void mma16816(float& d0, float& d1, float& d2, float& d3,
                                         u32 a0, u32 a1, u32 a2, u32 a3, u32 b0, u32 b1) {
    asm("mma.sync.aligned.m16n8k16.row.col.f32.bf16.bf16.f32 "
        "{%0,%1,%2,%3},{%4,%5,%6,%7},{%8,%9},{%0,%1,%2,%3};"
        : "+f"(d0), "+f"(d1), "+f"(d2), "+f"(d3)
        : "r"(a0), "r"(a1), "r"(a2), "r"(a3), "r"(b0), "r"(b1));
}

extern __shared__ char dynsm[];

// phase-4 multi-row worker
template<int NR>
__device__ __forceinline__ void quad_rows(const u64* __restrict__ hu,
                                          const float* __restrict__ alpha,
                                          u64* __restrict__ outu,
                                          int bb, int r0, int lane)
{
    u64 acc[NR][2];
    #pragma unroll
    for (int r = 0; r < NR; ++r) { acc[r][0] = 0; acc[r][1] = 0; }
    #pragma unroll 2
    for (int jb = 0; jb < 12; ++jb) {
        float4 a4[NR];
        #pragma unroll
        for (int r = 0; r < NR; ++r)
            a4[r] = *(const float4*)(alpha + (r0 + r) * ASTR + jb * 4);
        #pragma unroll
        for (int jj = 0; jj < 4; ++jj) {
            int j = jb * 4 + jj;
            u64 hlo = hu[j * HUSTR + lane];
            u64 hhi = hu[j * HUSTR + 32 + lane];
            #pragma unroll
            for (int r = 0; r < NR; ++r) {
                float av = (jj == 0) ? a4[r].x : (jj == 1) ? a4[r].y : (jj == 2) ? a4[r].z : a4[r].w;
                u64 c = f2_dup(av);
                acc[r][0] = f2_fma(c, hlo, acc[r][0]);
                acc[r][1] = f2_fma(c, hhi, acc[r][1]);
            }
        }
    }
    #pragma unroll
    for (int jj = 0; jj < 2; ++jj) {              // tail j = 48, 49
        int j = 48 + jj;
        u64 hlo = hu[j * HUSTR + lane];
        u64 hhi = hu[j * HUSTR + 32 + lane];
        #pragma unroll
        for (int r = 0; r < NR; ++r) {
            u64 c = f2_dup(alpha[(r0 + r) * ASTR + j]);
            acc[r][0] = f2_fma(c, hlo, acc[r][0]);
            acc[r][1] = f2_fma(c, hhi, acc[r][1]);
        }
    }
    size_t ob = (size_t)bb * (N_SZ * 64);
    #pragma unroll
    for (int r = 0; r < NR; ++r) {
        outu[ob + (r0 + r) * 64 + lane]      = acc[r][0];
        outu[ob + (r0 + r) * 64 + 32 + lane] = acc[r][1];
    }
}

// select accumulator by adj code c in 1..4
__device__ __forceinline__ float ksel(float d0, float d1, float d2, float d3, int c) {
    float v = d0;
    v = (c == 2) ? d1 : v;
    v = (c == 3) ? d2 : v;
    v = (c == 4) ? d3 : v;
    return v;
}

__global__ __launch_bounds__(NTHREADS, 2)
void session_graph_kernel(const int* __restrict__ inputs,
                          const int* __restrict__ adj,
                          const float* __restrict__ A_attr,
                          const float* __restrict__ emb,
                          const float* __restrict__ attr_emb,
                          const float* __restrict__ a0,
                          const float* __restrict__ a1,
                          const float* __restrict__ a2,
                          const float* __restrict__ a3,
                          float* __restrict__ out)
{
    const int tid  = threadIdx.x;
    const int bb   = blockIdx.x;
    const int warp = tid >> 5;
    const int lane = tid & 31;
    const int gq   = lane >> 2;
    const int tq   = lane & 3;
    u64* outu = (u64*)out;

    float* alpha = (float*)(dynsm + OFF_ALPHA);
    unsigned char* adjb = (unsigned char*)(dynsm + OFF_ADJ);
    const u64* hu = (const u64*)(dynsm + OFF_HU);

    // ---------------- staging -----------------------------------------
    if (tid < 256) {
        int k = tid >> 6, r = tid & 63, ks = r >> 2, q = r & 3;
        const float* a = (k == 0) ? a0 : (k == 1) ? a1 : (k == 2) ? a2 : a3;
        float s = (ks < 8) ? 0.6f : 0.4f;
        int bc = (ks & 7) * 16;
        u32 lo = bpack(s * a[bc + 2 * q],     s * a[bc + 2 * q + 1]);
        u32 hi = bpack(s * a[bc + 8 + 2 * q], s * a[bc + 8 + 2 * q + 1]);
        *(u64*)(dynsm + OFF_AB2 + ((k * 16 + ks) * 4 + q) * 8) = ((u64)hi << 32) | lo;
    }
    {
        const int4* ag4 = (const int4*)(adj + bb * NN);
        u32* adjw = (u32*)adjb;
        for (int idx = tid; idx < NN / 4; idx += NTHREADS) {
            int4 v = ag4[idx];
            adjw[idx] = (u32)(v.x & 255) | ((u32)(v.y & 255) << 8) |
                        ((u32)(v.z & 255) << 16) | ((u32)(v.w & 255) << 24);
        }
    }
    {
        const int* inrow = inputs + bb * N_SZ;
        const u64* embu = (const u64*)emb;
        for (int idx = tid; idx < N_SZ * 64; idx += NTHREADS) {
            int i = idx >> 6, c = idx & 63;
            int node = inrow[i];
            u64 e = embu[(size_t)node * 64 + c];
            *(u64*)(dynsm + OFF_HU + ((size_t)i * HUSTR + c) * 8) = e;
            *(u32*)(dynsm + OFF_HB16 + i * HBSTR + c * 4)       = bcvt(e);
            *(u32*)(dynsm + OFF_HB16 + i * HBSTR + 256 + c * 4) = bcvt(f2_abs(e));
        }
        for (int idx = tid; idx < 6 * 132; idx += NTHREADS) {    // zero rows 50..55
            int i = 50 + idx / 132, c = idx % 132;
            *(u32*)(dynsm + OFF_HB16 + i * HBSTR + c * 4) = 0;
        }
    }
    {
        float4 nv = make_float4(NEGV, NEGV, NEGV, NEGV);
        float4* al4 = (float4*)alpha;
        for (int idx = tid; idx < N_SZ * ASTR / 4; idx += NTHREADS)
            al4[idx] = nv;
    }
    __syncthreads();

    // ---------------- phase 2: ks outer, all 4 k inner (LDSM x1) -------
    {
        const u32 hbb = s2u(dynsm + OFF_HB16);
        const int grp = lane >> 3, rsel = lane & 7;
        const int ib = warp >> 2, np = warp & 3;
        int arow = ib * 16 + rsel + ((grp & 1) << 3);
        if (arow >= N_SZ) arow = 0;                     // discarded rows
        const u32 aaddr = hbb + arow * HBSTR + ((grp >> 1) << 4);
        const int nt0 = np * 2;
        const u32 baddr0 = hbb + (nt0 * 8 + rsel) * HBSTR + ((lane & 8) << 1);
        const u32 baddr1 = baddr0 + 8 * HBSTR;
        const bool pair = (np < 3);
        const int i0 = ib * 16 + gq, i1 = i0 + 8;
        const int j0 = nt0 * 8 + 2 * tq;
        const u64* abp = (const u64*)(dynsm + OFF_AB2) + tq;

        float dA[4][4], dB[4][4];
        #pragma unroll
        for (int k = 0; k < 4; ++k)
            #pragma unroll
            for (int x = 0; x < 4; ++x) { dA[k][x] = 0.f; dB[k][x] = 0.f; }

        #pragma unroll 4
        for (int ks = 0; ks < 16; ++ks) {
            u32 h0, h1, h2, h3;
            ldsm4(h0, h1, h2, h3, aaddr + ks * 32);
            u32 b0, b1, c0, c1;
            ldsm2(b0, b1, baddr0 + ks * 32);
            if (pair) ldsm2(c0, c1, baddr1 + ks * 32);
            #pragma unroll
            for (int k = 0; k < 4; ++k) {
                u64 ab = abp[k * 64 + ks * 4];
                u32 lo = (u32)ab, hi = (u32)(ab >> 32);
                u32 f0 = bmul(h0, lo), f1 = bmul(h1, lo);
                u32 f2 = bmul(h2, hi), f3 = bmul(h3, hi);
                mma16816(dA[k][0], dA[k][1], dA[k][2], dA[k][3], f0, f1, f2, f3, b0, b1);
                if (pair)
                    mma16816(dB[k][0], dB[k][1], dB[k][2], dB[k][3], f0, f1, f2, f3, c0, c1);
            }
        }

        // epilogue: one adj read + k-select per cell
        #pragma unroll
        for (int pos = 0; pos < 4; ++pos) {
            int i = (pos < 2) ? i0 : i1;
            int j = j0 + (pos & 1);
            if (i < N_SZ && j < N_SZ) {
                int c = adjb[i * N_SZ + j];
                if (c) alpha[i * ASTR + j] =
                    ksel(dA[0][pos], dA[1][pos], dA[2][pos], dA[3][pos], c);
            }
            if (pair) {
                int j2 = j + 8;
                if (i < N_SZ && j2 < N_SZ) {
                    int c = adjb[i * N_SZ + j2];
                    if (c) alpha[i * ASTR + j2] =
                        ksel(dB[0][pos], dB[1][pos], dB[2][pos], dB[3][pos], c);
                }
            }
        }
    }
    __syncthreads();

    // ---------------- phase 3: row softmax ------------------------------
    for (int i = warp; i < N_SZ; i += 16) {
        float v0 = alpha[i * ASTR + lane];
        float v1 = (lane < N_SZ - 32) ? alpha[i * ASTR + 32 + lane] : NEGV;
        float m = fmaxf(v0, v1);
        #pragma unroll
        for (int off = 16; off > 0; off >>= 1)
            m = fmaxf(m, __shfl_xor_sync(0xFFFFFFFFu, m, off));
        float e0 = __expf(v0 - m);
        float e1 = (lane < N_SZ - 32) ? __expf(v1 - m) : 0.f;
        float ss = e0 + e1;
        #pragma unroll
        for (int off = 16; off > 0; off >>= 1)
            ss += __shfl_xor_sync(0xFFFFFFFFu, ss, off);
        float inv = 1.0f / ss;
        alpha[i * ASTR + lane] = e0 * inv;
        if (lane < N_SZ - 32)
            alpha[i * ASTR + 32 + lane] = e1 * inv;
    }
    __syncthreads();

    // ---------------- phase 4: out = alpha @ h (5 rows x 10 warps) -----
    // warps 10-15 skip straight to the attr partial (no smem dependency)
    if (warp < 10) quad_rows<5>(hu, alpha, outu, bb, warp * 5, lane);

    // ---------------- attr partial: group bb>>3, K-slice bb&7 -----------
    // 8 rows x 250 k, weighted warp split (warps 10-15 take more k).
    u64 acc[ATTR_ROWS][2];
    {
        const int g     = bb >> 3;
        const int kbase = (bb & 7) * 250;
        const float* Arow = A_attr + (size_t)(g * ATTR_ROWS) * MAX_ATTR + kbase;
        const uint4* Wg = (const uint4*)attr_emb;

        int c0, c1;
        if (warp >= 10)    { c0 = 13 * (warp - 10);    c1 = c0 + 13; }   // 0..77
        else if (warp < 7) { c0 = 78 + 5 * warp;       c1 = c0 + 5;  }   // 78..112
        else               { c0 = 113 + 4 * (warp - 7); c1 = c0 + 4; }   // 113..124

        #pragma unroll
        for (int r = 0; r < ATTR_ROWS; ++r) { acc[r][0] = 0; acc[r][1] = 0; }

        for (int c = c0; c < c1; ++c) {
            int k = kbase + 2 * c;
            uint4 w0 = Wg[(size_t)k * 32 + lane];
            uint4 w1 = Wg[(size_t)(k + 1) * 32 + lane];
            u64 w0l = ((u64)w0.y << 32) | w0.x, w0h = ((u64)w0.w << 32) | w0.z;
            u64 w1l = ((u64)w1.y << 32) | w1.x, w1h = ((u64)w1.w << 32) | w1.z;
            #pragma unroll
            for (int r = 0; r < ATTR_ROWS; ++r) {
                float2 a = *(const float2*)(Arow + r * MAX_ATTR + 2 * c);
                u64 cx = f2_dup(a.x), cy = f2_dup(a.y);
                acc[r][0] = f2_fma(cx, w0l, acc[r][0]);
                acc[r][1] = f2_fma(cx, w0h, acc[r][1]);
                acc[r][0] = f2_fma(cy, w1l, acc[r][0]);
                acc[r][1] = f2_fma(cy, w1h, acc[r][1]);
            }
        }
    }

    // ---------------- cross-warp reduce in smem, then 2 atomics/thread --
    __syncthreads();                        // phase 4 + partials done; smem dead
    {
        u64* red = (u64*)dynsm;             // 16 x 8 x 64 u64 = 64 KB
        #pragma unroll
        for (int r = 0; r < ATTR_ROWS; ++r) {
            u64* myred = red + ((size_t)(warp * ATTR_ROWS + r)) * 64;
            myred[2 * lane]     = acc[r][0];
            myred[2 * lane + 1] = acc[r][1];
        }
        __syncthreads();

        int row = tid >> 6, col = tid & 63;
        u64 s = 0;
        #pragma unroll
        for (int w = 0; w < 16; ++w)
            s = f2_add(s, red[((size_t)(w * ATTR_ROWS + row)) * 64 + col]);
        float2 v = f2_unpack(s);
        const int g = bb >> 3;
        float* dst = out + (size_t)B_SZ * (N_SZ * 128)
                         + (size_t)(g * ATTR_ROWS + row) * 128 + col * 2;
        atomicAdd(dst,     v.x);
        atomicAdd(dst + 1, v.y);
    }
}

extern "C" void kernel_launch(void* const* d_in, const int* in_sizes, int n_in,
                              void* d_out, int out_size)
{
    (void)in_sizes; (void)n_in; (void)out_size;
    const int*   inputs    = (const int*)  d_in[0];
    const int*   adj       = (const int*)  d_in[1];
    // d_in[2] = mask_item (unused by the reference computation)
    const float* A_attr    = (const float*)d_in[3];
    const float* emb       = (const float*)d_in[4];
    const float* attr_emb  = (const float*)d_in[5];
    const float* a0        = (const float*)d_in[6];
    const float* a1        = (const float*)d_in[7];
    const float* a2        = (const float*)d_in[8];
    const float* a3        = (const float*)d_in[9];
    float* out = (float*)d_out;

    // zero the attr_sess region (accumulated via atomics)
    cudaMemsetAsync(out + (size_t)B_SZ * N_SZ * 128, 0,
                    (size_t)B_SZ * 128 * sizeof(float));

    cudaFuncSetAttribute(session_graph_kernel,
                         cudaFuncAttributeMaxDynamicSharedMemorySize, SMEM_DYN);
    session_graph_kernel<<<B_SZ, NTHREADS, SMEM_DYN>>>(
        inputs, adj, A_attr, emb, attr_emb, a0, a1, a2, a3, out);
}

// round 16
// speedup vs baseline: 1.7170x; 1.0600x over previous
#include <cuda_runtime.h>

typedef unsigned long long u64;
typedef unsigned int u32;

#define B_SZ 256
#define N_SZ 50
#define NN   (N_SZ * N_SZ)
#define MAX_ATTR 2000
#define NEGV (-9e15f)
#define NTHREADS 512
#define ATTR_ROWS 8
#define AQ_BLOCKS 256           // 32 groups x 8 K-slices (250 k each)
#define HBSTR 528               // bytes per hb16 row (264 bf16)
#define HUSTR 65                // u64 stride per fp32 h row
#define ASTR  56                // alpha row stride (f32)

// ---- dynamic smem layout (session) -----------------------------------------
#define OFF_HB16  0
#define SZ_HB16   (56 * HBSTR)                 // 29568
#define OFF_HU    (OFF_HB16 + SZ_HB16)
#define SZ_HU     (N_SZ * HUSTR * 8)           // 26000
#define OFF_AB2   (OFF_HU + SZ_HU)
#define SZ_AB2    (4 * 16 * 4 * 8)             // 2048
#define OFF_ALPHA (OFF_AB2 + SZ_AB2)
#define SZ_ALPHA  (N_SZ * ASTR * 4)            // 11200
#define OFF_ADJ   (OFF_ALPHA + SZ_ALPHA)
#define SZ_ADJ    2560
#define SMEM_DYN  (OFF_ADJ + SZ_ADJ)           // 71376 (attr blocks use 0..65536 for reduce)

// ---- helpers ---------------------------------------------------------------
__device__ __forceinline__ u64 f2_fma(u64 a, u64 b, u64 c) {
    u64 d; asm("fma.rn.f32x2 %0,%1,%2,%3;" : "=l"(d) : "l"(a), "l"(b), "l"(c)); return d;
}
__device__ __forceinline__ u64 f2_add(u64 a, u64 b) {
    u64 d; asm("add.rn.f32x2 %0,%1,%2;" : "=l"(d) : "l"(a), "l"(b)); return d;
}
__device__ __forceinline__ u64 f2_abs(u64 a) { return a & 0x7FFFFFFF7FFFFFFFull; }
__device__ __forceinline__ u64 f2_dup(float a) {
    u64 d; asm("mov.b64 %0,{%1,%1};" : "=l"(d) : "f"(a)); return d;
}
__device__ __forceinline__ float2 f2_unpack(u64 a) {
    float2 r; asm("mov.b64 {%0,%1},%2;" : "=f"(r.x), "=f"(r.y) : "l"(a)); return r;
}
__device__ __forceinline__ u32 bpack(float lo, float hi) {
    u32 r; asm("cvt.rn.bf16x2.f32 %0,%1,%2;" : "=r"(r) : "f"(hi), "f"(lo)); return r;
}
__device__ __forceinline__ u32 bcvt(u64 v) {
    float2 p = f2_unpack(v); return bpack(p.x, p.y);
}
__device__ __forceinline__ u32 bmul(u32 a, u32 b) {
    u32 d; asm("mul.bf16x2 %0,%1,%2;" : "=r"(d) : "r"(a), "r"(b)); return d;
}
__device__ __forceinline__ u32 s2u(const void* p) {
    u32 a; asm("{.reg .u64 t; cvta.to.shared.u64 t,%1; cvt.u32.u64 %0,t;}" : "=r"(a) : "l"(p));
    return a;
}
__device__ __forceinline__ void ldsm4(u32& r0, u32& r1, u32& r2, u32& r3, u32 addr) {
    asm volatile("ldmatrix.sync.aligned.m8n8.x4.shared.b16 {%0,%1,%2,%3},[%4];"
                 : "=r"(r0), "=r"(r1), "=r"(r2), "=r"(r3) : "r"(addr));
}
__device__ __forceinline__ void ldsm2(u32& r0, u32& r1, u32 addr) {
    asm volatile("ldmatrix.sync.aligned.m8n8.x2.shared.b16 {%0,%1},[%2];"
                 : "=r"(r0), "=r"(r1) : "r"(addr));
}
__device__ __forceinline__ void mma16816(float& d0, float& d1, float& d2, float& d3,
                                         u32 a0, u32 a1, u32 a2, u32 a3, u32 b0, u32 b1) {
    asm("mma.sync.aligned.m16n8k16.row.col.f32.bf16.bf16.f32 "
        "{%0,%1,%2,%3},{%4,%5,%6,%7},{%8,%9},{%0,%1,%2,%3};"
        : "+f"(d0), "+f"(d1), "+f"(d2), "+f"(d3)
        : "r"(a0), "r"(a1), "r"(a2), "r"(a3), "r"(b0), "r"(b1));
}

extern __shared__ char dynsm[];

// phase-4 multi-row worker
template<int NR>
__device__ __forceinline__ void quad_rows(const u64* __restrict__ hu,
                                          const float* __restrict__ alpha,
                                          u64* __restrict__ outu,
                                          int bb, int r0, int lane)
{
    u64 acc[NR][2];
    #pragma unroll
    for (int r = 0; r < NR; ++r) { acc[r][0] = 0; acc[r][1] = 0; }
    #pragma unroll 2
    for (int jb = 0; jb < 12; ++jb) {
        float4 a4[NR];
        #pragma unroll
        for (int r = 0; r < NR; ++r)
            a4[r] = *(const float4*)(alpha + (r0 + r) * ASTR + jb * 4);
        #pragma unroll
        for (int jj = 0; jj < 4; ++jj) {
            int j = jb * 4 + jj;
            u64 hlo = hu[j * HUSTR + lane];
            u64 hhi = hu[j * HUSTR + 32 + lane];
            #pragma unroll
            for (int r = 0; r < NR; ++r) {
                float av = (jj == 0) ? a4[r].x : (jj == 1) ? a4[r].y : (jj == 2) ? a4[r].z : a4[r].w;
                u64 c = f2_dup(av);
                acc[r][0] = f2_fma(c, hlo, acc[r][0]);
                acc[r][1] = f2_fma(c, hhi, acc[r][1]);
            }
        }
    }
    #pragma unroll
    for (int jj = 0; jj < 2; ++jj) {              // tail j = 48, 49
        int j = 48 + jj;
        u64 hlo = hu[j * HUSTR + lane];
        u64 hhi = hu[j * HUSTR + 32 + lane];
        #pragma unroll
        for (int r = 0; r < NR; ++r) {
            u64 c = f2_dup(alpha[(r0 + r) * ASTR + j]);
            acc[r][0] = f2_fma(c, hlo, acc[r][0]);
            acc[r][1] = f2_fma(c, hhi, acc[r][1]);
        }
    }
    size_t ob = (size_t)bb * (N_SZ * 64);
    #pragma unroll
    for (int r = 0; r < NR; ++r) {
        outu[ob + (r0 + r) * 64 + lane]      = acc[r][0];
        outu[ob + (r0 + r) * 64 + 32 + lane] = acc[r][1];
    }
}

// select accumulator by adj code c in 1..4
__device__ __forceinline__ float ksel(float d0, float d1, float d2, float d3, int c) {
    float v = d0;
    v = (c == 2) ? d1 : v;
    v = (c == 3) ? d2 : v;
    v = (c == 4) ? d3 : v;
    return v;
}

__global__ __launch_bounds__(NTHREADS, 2)
void session_graph_kernel(const int* __restrict__ inputs,
                          const int* __restrict__ adj,
                          const float* __restrict__ A_attr,
                          const float* __restrict__ emb,
                          const float* __restrict__ attr_emb,
                          const float* __restrict__ a0,
                          const float* __restrict__ a1,
                          const float* __restrict__ a2,
                          const float* __restrict__ a3,
                          float* __restrict__ out)
{
    const int tid  = threadIdx.x;
    const int bb   = blockIdx.x;
    const int warp = tid >> 5;
    const int lane = tid & 31;
    const int gq   = lane >> 2;
    const int tq   = lane & 3;
    u64* outu = (u64*)out;

    if (bb < B_SZ) {
        // ================== session block (pure, no attr) ==================
        float* alpha = (float*)(dynsm + OFF_ALPHA);
        unsigned char* adjb = (unsigned char*)(dynsm + OFF_ADJ);
        const u64* hu = (const u64*)(dynsm + OFF_HU);

        // ---------------- staging -----------------------------------------
        if (tid < 256) {
            int k = tid >> 6, r = tid & 63, ks = r >> 2, q = r & 3;
            const float* a = (k == 0) ? a0 : (k == 1) ? a1 : (k == 2) ? a2 : a3;
            float s = (ks < 8) ? 0.6f : 0.4f;
            int bc = (ks & 7) * 16;
            u32 lo = bpack(s * a[bc + 2 * q],     s * a[bc + 2 * q + 1]);
            u32 hi = bpack(s * a[bc + 8 + 2 * q], s * a[bc + 8 + 2 * q + 1]);
            *(u64*)(dynsm + OFF_AB2 + ((k * 16 + ks) * 4 + q) * 8) = ((u64)hi << 32) | lo;
        }
        {
            const int4* ag4 = (const int4*)(adj + bb * NN);
            u32* adjw = (u32*)adjb;
            for (int idx = tid; idx < NN / 4; idx += NTHREADS) {
                int4 v = ag4[idx];
                adjw[idx] = (u32)(v.x & 255) | ((u32)(v.y & 255) << 8) |
                            ((u32)(v.z & 255) << 16) | ((u32)(v.w & 255) << 24);
            }
        }
        {
            const int* inrow = inputs + bb * N_SZ;
            const u64* embu = (const u64*)emb;
            for (int idx = tid; idx < N_SZ * 64; idx += NTHREADS) {
                int i = idx >> 6, c = idx & 63;
                int node = inrow[i];
                u64 e = embu[(size_t)node * 64 + c];
                *(u64*)(dynsm + OFF_HU + ((size_t)i * HUSTR + c) * 8) = e;
                *(u32*)(dynsm + OFF_HB16 + i * HBSTR + c * 4)       = bcvt(e);
                *(u32*)(dynsm + OFF_HB16 + i * HBSTR + 256 + c * 4) = bcvt(f2_abs(e));
            }
            for (int idx = tid; idx < 6 * 132; idx += NTHREADS) {    // zero rows 50..55
                int i = 50 + idx / 132, c = idx % 132;
                *(u32*)(dynsm + OFF_HB16 + i * HBSTR + c * 4) = 0;
            }
        }
        {
            float4 nv = make_float4(NEGV, NEGV, NEGV, NEGV);
            float4* al4 = (float4*)alpha;
            for (int idx = tid; idx < N_SZ * ASTR / 4; idx += NTHREADS)
                al4[idx] = nv;
        }
        __syncthreads();

        // ---------------- phase 2: ks outer, all 4 k inner (LDSM x1) -------
        {
            const u32 hbb = s2u(dynsm + OFF_HB16);
            const int grp = lane >> 3, rsel = lane & 7;
            const int ib = warp >> 2, np = warp & 3;
            int arow = ib * 16 + rsel + ((grp & 1) << 3);
            if (arow >= N_SZ) arow = 0;                     // discarded rows
            const u32 aaddr = hbb + arow * HBSTR + ((grp >> 1) << 4);
            const int nt0 = np * 2;
            const u32 baddr0 = hbb + (nt0 * 8 + rsel) * HBSTR + ((lane & 8) << 1);
            const u32 baddr1 = baddr0 + 8 * HBSTR;
            const bool pair = (np < 3);
            const int i0 = ib * 16 + gq, i1 = i0 + 8;
            const int j0 = nt0 * 8 + 2 * tq;
            const u64* abp = (const u64*)(dynsm + OFF_AB2) + tq;

            float dA[4][4], dB[4][4];
            #pragma unroll
            for (int k = 0; k < 4; ++k)
                #pragma unroll
                for (int x = 0; x < 4; ++x) { dA[k][x] = 0.f; dB[k][x] = 0.f; }

            #pragma unroll 4
            for (int ks = 0; ks < 16; ++ks) {
                u32 h0, h1, h2, h3;
                ldsm4(h0, h1, h2, h3, aaddr + ks * 32);
                u32 b0, b1, c0, c1;
                ldsm2(b0, b1, baddr0 + ks * 32);
                if (pair) ldsm2(c0, c1, baddr1 + ks * 32);
                #pragma unroll
                for (int k = 0; k < 4; ++k) {
                    u64 ab = abp[k * 64 + ks * 4];
                    u32 lo = (u32)ab, hi = (u32)(ab >> 32);
                    u32 f0 = bmul(h0, lo), f1 = bmul(h1, lo);
                    u32 f2 = bmul(h2, hi), f3 = bmul(h3, hi);
                    mma16816(dA[k][0], dA[k][1], dA[k][2], dA[k][3], f0, f1, f2, f3, b0, b1);
                    if (pair)
                        mma16816(dB[k][0], dB[k][1], dB[k][2], dB[k][3], f0, f1, f2, f3, c0, c1);
                }
            }

            // epilogue: one adj read + k-select per cell
            #pragma unroll
            for (int pos = 0; pos < 4; ++pos) {
                int i = (pos < 2) ? i0 : i1;
                int j = j0 + (pos & 1);
                if (i < N_SZ && j < N_SZ) {
                    int c = adjb[i * N_SZ + j];
                    if (c) alpha[i * ASTR + j] =
                        ksel(dA[0][pos], dA[1][pos], dA[2][pos], dA[3][pos], c);
                }
                if (pair) {
                    int j2 = j + 8;
                    if (i < N_SZ && j2 < N_SZ) {
                        int c = adjb[i * N_SZ + j2];
                        if (c) alpha[i * ASTR + j2] =
                            ksel(dB[0][pos], dB[1][pos], dB[2][pos], dB[3][pos], c);
                    }
                }
            }
        }
        __syncthreads();

        // ---------------- phase 3: row softmax ------------------------------
        for (int i = warp; i < N_SZ; i += 16) {
            float v0 = alpha[i * ASTR + lane];
            float v1 = (lane < N_SZ - 32) ? alpha[i * ASTR + 32 + lane] : NEGV;
            float m = fmaxf(v0, v1);
            #pragma unroll
            for (int off = 16; off > 0; off >>= 1)
                m = fmaxf(m, __shfl_xor_sync(0xFFFFFFFFu, m, off));
            float e0 = __expf(v0 - m);
            float e1 = (lane < N_SZ - 32) ? __expf(v1 - m) : 0.f;
            float ss = e0 + e1;
            #pragma unroll
            for (int off = 16; off > 0; off >>= 1)
                ss += __shfl_xor_sync(0xFFFFFFFFu, ss, off);
            float inv = 1.0f / ss;
            alpha[i * ASTR + lane] = e0 * inv;
            if (lane < N_SZ - 32)
                alpha[i * ASTR + 32 + lane] = e1 * inv;
        }
        __syncthreads();

        // ---------------- phase 4: out = alpha @ h (5 rows x 10 warps) -----
        if (warp < 10) quad_rows<5>(hu, alpha, outu, bb, warp * 5, lane);
    } else {
        // ================== attr micro-block: group g, K-slice s ===========
        // 8 rows x 250 k; 256 such blocks drain through spare SM slots
        // concurrently with the session blocks.
        const int ab = bb - B_SZ;            // 0..255
        const int g  = ab >> 3;              // row group (32)
        const int sl = ab & 7;               // K slice (8)
        const int r0row = g * ATTR_ROWS;
        const int kbase = sl * 250;

        const float* Arow = A_attr + (size_t)r0row * MAX_ATTR + kbase;
        const uint4* Wg = (const uint4*)attr_emb;

        u64 acc[ATTR_ROWS][2];
        #pragma unroll
        for (int r = 0; r < ATTR_ROWS; ++r) { acc[r][0] = 0; acc[r][1] = 0; }

        // 125 float2-chunks of k, interleaved across 16 warps
        for (int c = warp; c < 125; c += 16) {
            int k = kbase + 2 * c;
            uint4 w0 = Wg[(size_t)k * 32 + lane];
            uint4 w1 = Wg[(size_t)(k + 1) * 32 + lane];
            u64 w0l = ((u64)w0.y << 32) | w0.x, w0h = ((u64)w0.w << 32) | w0.z;
            u64 w1l = ((u64)w1.y << 32) | w1.x, w1h = ((u64)w1.w << 32) | w1.z;
            #pragma unroll
            for (int r = 0; r < ATTR_ROWS; ++r) {
                float2 a = *(const float2*)(Arow + r * MAX_ATTR + 2 * c);
                u64 cx = f2_dup(a.x), cy = f2_dup(a.y);
                acc[r][0] = f2_fma(cx, w0l, acc[r][0]);
                acc[r][1] = f2_fma(cx, w0h, acc[r][1]);
                acc[r][0] = f2_fma(cy, w1l, acc[r][0]);
                acc[r][1] = f2_fma(cy, w1h, acc[r][1]);
            }
        }

        // cross-warp reduce in smem, then 2 atomics per thread
        u64* red = (u64*)dynsm;              // 16 x 8 x 64 u64 = 64 KB
        #pragma unroll
        for (int r = 0; r < ATTR_ROWS; ++r) {
            u64* myred = red + ((size_t)(warp * ATTR_ROWS + r)) * 64;
            myred[2 * lane]     = acc[r][0];
            myred[2 * lane + 1] = acc[r][1];
        }
        __syncthreads();

        {
            int row = tid >> 6, col = tid & 63;
            u64 s = 0;
            #pragma unroll
            for (int w = 0; w < 16; ++w)
                s = f2_add(s, red[((size_t)(w * ATTR_ROWS + row)) * 64 + col]);
            float2 v = f2_unpack(s);
            float* dst = out + (size_t)B_SZ * (N_SZ * 128)
                             + (size_t)(r0row + row) * 128 + col * 2;
            atomicAdd(dst,     v.x);
            atomicAdd(dst + 1, v.y);
        }
    }
}

extern "C" void kernel_launch(void* const* d_in, const int* in_sizes, int n_in,
                              void* d_out, int out_size)
{
    (void)in_sizes; (void)n_in; (void)out_size;
    const int*   inputs    = (const int*)  d_in[0];
    const int*   adj       = (const int*)  d_in[1];
    // d_in[2] = mask_item (unused by the reference computation)
    const float* A_attr    = (const float*)d_in[3];
    const float* emb       = (const float*)d_in[4];
    const float* attr_emb  = (const float*)d_in[5];
    const float* a0        = (const float*)d_in[6];
    const float* a1        = (const float*)d_in[7];
    const float* a2        = (const float*)d_in[8];
    const float* a3        = (const float*)d_in[9];
    float* out = (float*)d_out;

    // zero the attr_sess region (accumulated via atomics)
    cudaMemsetAsync(out + (size_t)B_SZ * N_SZ * 128, 0,
                    (size_t)B_SZ * 128 * sizeof(float));

    cudaFuncSetAttribute(session_graph_kernel,
                         cudaFuncAttributeMaxDynamicSharedMemorySize, SMEM_DYN);
    session_graph_kernel<<<B_SZ + AQ_BLOCKS, NTHREADS, SMEM_DYN>>>(
        inputs, adj, A_attr, emb, attr_emb, a0, a1, a2, a3, out);
}